// round 3
// baseline (speedup 1.0000x reference)
#include <cuda_runtime.h>

// Problem constants (fixed by setup_inputs)
#define NB 16
#define H 768
#define W 768
#define HW (H * W)          // 589824
#define NHW (NB * HW)       // 9437184

// Ping-pong scratch for interleaved disp (float2 = (dx, dy)) — static, no alloc.
__device__ float2 g_bufA[NHW];
__device__ float2 g_bufB[NHW];

// ---------------------------------------------------------------------------
// Zero the num_touch region of d_out (poisoned to 0xAA by the harness).
// ---------------------------------------------------------------------------
__global__ void zero_touch(float* __restrict__ nt) {
    int i = blockIdx.x * blockDim.x + threadIdx.x;
    if (i < NHW) nt[i] = 0.0f;
}

// ---------------------------------------------------------------------------
// Iteration 1: planar pred_disp [N,2,H,W] -> interleaved float2 out.
// ---------------------------------------------------------------------------
__global__ void iter_first(const float* __restrict__ in, float2* __restrict__ out) {
    const int p = blockIdx.x * blockDim.x + threadIdx.x;   // pixel within image
    if (p >= HW) return;
    const int n = blockIdx.y;
    const int y = p / W;
    const int x = p - y * W;

    const float* base = in + (size_t)n * 2 * HW;
    const float dx = base[p];
    const float dy = base[HW + p];

    int cx = (int)((float)x + dx);   // trunc toward zero, same as .astype(int32)
    int cy = (int)((float)y + dy);
    cx = min(max(cx, 0), W - 1);
    cy = min(max(cy, 0), H - 1);
    const int gp = cy * W + cx;

    const float gx = base[gp];
    const float gy = base[HW + gp];

    out[(size_t)n * HW + p] = make_float2(dx + gx, dy + gy);
}

// ---------------------------------------------------------------------------
// Iterations 2,3: interleaved -> interleaved.
// ---------------------------------------------------------------------------
__global__ void iter_mid(const float2* __restrict__ in, float2* __restrict__ out) {
    const int p = blockIdx.x * blockDim.x + threadIdx.x;
    if (p >= HW) return;
    const int n = blockIdx.y;
    const int y = p / W;
    const int x = p - y * W;

    const float2* base = in + (size_t)n * HW;
    const float2 d = base[p];

    int cx = (int)((float)x + d.x);
    int cy = (int)((float)y + d.y);
    cx = min(max(cx, 0), W - 1);
    cy = min(max(cy, 0), H - 1);

    const float2 g = base[cy * W + cx];

    out[(size_t)n * HW + p] = make_float2(d.x + g.x, d.y + g.y);
}

// ---------------------------------------------------------------------------
// Iteration 4 (final): interleaved in -> planar disp out, num_touch scatter-add,
// pred_cent write. All outputs as float32 (harness output dtype).
//   d_out layout: [disp: 2*NHW][num_touch: NHW][pred_cent: 3*NHW]
// ---------------------------------------------------------------------------
__global__ void iter_last(const float2* __restrict__ in,
                          float* __restrict__ disp_out,
                          float* __restrict__ nt_out,
                          float* __restrict__ pc_out) {
    const int p = blockIdx.x * blockDim.x + threadIdx.x;
    if (p >= HW) return;
    const int n = blockIdx.y;
    const int y = p / W;
    const int x = p - y * W;

    const float2* base = in + (size_t)n * HW;
    const float2 d = base[p];

    int cx = (int)((float)x + d.x);
    int cy = (int)((float)y + d.y);
    cx = min(max(cx, 0), W - 1);
    cy = min(max(cy, 0), H - 1);
    const int gp = cy * W + cx;

    const float2 g = base[gp];

    // disp out (planar [N,2,H,W])
    float* db = disp_out + (size_t)n * 2 * HW;
    db[p]      = d.x + g.x;
    db[HW + p] = d.y + g.y;

    // num_touch scatter-add (counts are small integers; exact in f32)
    atomicAdd(&nt_out[(size_t)n * HW + gp], 1.0f);

    // pred_cent [N,3,H,W] = (b, cx, cy)
    float* pb = pc_out + (size_t)n * 3 * HW;
    pb[p]          = (float)n;
    pb[HW + p]     = (float)cx;
    pb[2 * HW + p] = (float)cy;
}

extern "C" void kernel_launch(void* const* d_in, const int* in_sizes, int n_in,
                              void* d_out, int out_size) {
    const float* pred_disp = (const float*)d_in[0];
    float* out = (float*)d_out;

    float* disp_out = out;                      // 2*NHW
    float* nt_out   = out + (size_t)2 * NHW;    // NHW
    float* pc_out   = out + (size_t)3 * NHW;    // 3*NHW

    float2* bufA;  cudaGetSymbolAddress((void**)&bufA, g_bufA);
    float2* bufB;  cudaGetSymbolAddress((void**)&bufB, g_bufB);

    const int T = 256;
    dim3 grid((HW + T - 1) / T, NB);

    zero_touch<<<(NHW + T - 1) / T, T>>>(nt_out);
    iter_first<<<grid, T>>>(pred_disp, bufA);   // it 1
    iter_mid  <<<grid, T>>>(bufA, bufB);        // it 2
    iter_mid  <<<grid, T>>>(bufB, bufA);        // it 3
    iter_last <<<grid, T>>>(bufA, disp_out, nt_out, pc_out);  // it 4
}

// round 5
// speedup vs baseline: 1.0420x; 1.0420x over previous
#include <cuda_runtime.h>

// Problem constants (fixed by setup_inputs)
#define NB 16
#define H 768
#define W 768
#define HW (H * W)          // 589824
#define NHW (NB * HW)       // 9437184

// Each thread handles 4 consecutive pixels (aligned; 768%4==0 so a chunk never
// crosses a row). 256 threads/block -> 1024 px/block; HW/1024 = 576 exact.
#define T 256
#define PPB (T * 4)                 // 1024
#define BLKS (HW / PPB)             // 576

// Ping-pong scratch for interleaved disp (float2 = (dx, dy)) — static, no alloc.
__device__ float2 g_bufA[NHW];
__device__ float2 g_bufB[NHW];

__device__ __forceinline__ int clampi(int v, int hi) {
    return min(max(v, 0), hi);
}

// ---------------------------------------------------------------------------
// Iteration 1: planar pred_disp [N,2,H,W] -> interleaved float2 out.
// Also zeroes the num_touch output region (harness poisons it to 0xAA).
// ---------------------------------------------------------------------------
__global__ void iter_first(const float* __restrict__ in, float2* __restrict__ out,
                           float* __restrict__ nt) {
    const int p = (blockIdx.x * T + threadIdx.x) * 4;  // first pixel of chunk
    const int n = blockIdx.y;
    const int y = p / W;
    const int x = p - y * W;

    const float* base = in + (size_t)n * 2 * HW;

    // coalesced vector loads of the 4 dx and 4 dy
    const float4 vx = *(const float4*)(base + p);
    const float4 vy = *(const float4*)(base + HW + p);

    float dx[4] = {vx.x, vx.y, vx.z, vx.w};
    float dy[4] = {vy.x, vy.y, vy.z, vy.w};

    int gp[4];
#pragma unroll
    for (int i = 0; i < 4; i++) {
        int cx = clampi((int)((float)(x + i) + dx[i]), W - 1);
        int cy = clampi((int)((float)y + dy[i]), H - 1);
        gp[i] = cy * W + cx;
    }

    // 8 independent scattered loads (batched for MLP)
    float gx[4], gy[4];
#pragma unroll
    for (int i = 0; i < 4; i++) gx[i] = base[gp[i]];
#pragma unroll
    for (int i = 0; i < 4; i++) gy[i] = base[HW + gp[i]];

    float2* ob = out + (size_t)n * HW + p;
    float4 o0 = make_float4(dx[0] + gx[0], dy[0] + gy[0], dx[1] + gx[1], dy[1] + gy[1]);
    float4 o1 = make_float4(dx[2] + gx[2], dy[2] + gy[2], dx[3] + gx[3], dy[3] + gy[3]);
    *(float4*)(ob)     = o0;
    *(float4*)(ob + 2) = o1;

    // zero num_touch for this chunk (same NHW index space)
    *(float4*)(nt + (size_t)n * HW + p) = make_float4(0.f, 0.f, 0.f, 0.f);
}

// ---------------------------------------------------------------------------
// Iterations 2,3: interleaved -> interleaved.
// ---------------------------------------------------------------------------
__global__ void iter_mid(const float2* __restrict__ in, float2* __restrict__ out) {
    const int p = (blockIdx.x * T + threadIdx.x) * 4;
    const int n = blockIdx.y;
    const int y = p / W;
    const int x = p - y * W;

    const float2* base = in + (size_t)n * HW;

    const float4 a = *(const float4*)(base + p);      // px 0,1
    const float4 b = *(const float4*)(base + p + 2);  // px 2,3
    float dx[4] = {a.x, a.z, b.x, b.z};
    float dy[4] = {a.y, a.w, b.y, b.w};

    int gp[4];
#pragma unroll
    for (int i = 0; i < 4; i++) {
        int cx = clampi((int)((float)(x + i) + dx[i]), W - 1);
        int cy = clampi((int)((float)y + dy[i]), H - 1);
        gp[i] = cy * W + cx;
    }

    float2 g[4];
#pragma unroll
    for (int i = 0; i < 4; i++) g[i] = base[gp[i]];   // 4 independent gathers

    float2* ob = out + (size_t)n * HW + p;
    float4 o0 = make_float4(dx[0] + g[0].x, dy[0] + g[0].y, dx[1] + g[1].x, dy[1] + g[1].y);
    float4 o1 = make_float4(dx[2] + g[2].x, dy[2] + g[2].y, dx[3] + g[3].x, dy[3] + g[3].y);
    *(float4*)(ob)     = o0;
    *(float4*)(ob + 2) = o1;
}

// ---------------------------------------------------------------------------
// Iteration 4 (final): interleaved in -> planar disp out, num_touch scatter-add,
// pred_cent write. All outputs as float32 (harness output dtype).
//   d_out layout: [disp: 2*NHW][num_touch: NHW][pred_cent: 3*NHW]
// ---------------------------------------------------------------------------
__global__ void iter_last(const float2* __restrict__ in,
                          float* __restrict__ disp_out,
                          float* __restrict__ nt_out,
                          float* __restrict__ pc_out) {
    const int p = (blockIdx.x * T + threadIdx.x) * 4;
    const int n = blockIdx.y;
    const int y = p / W;
    const int x = p - y * W;

    const float2* base = in + (size_t)n * HW;

    const float4 a = *(const float4*)(base + p);
    const float4 b = *(const float4*)(base + p + 2);
    float dx[4] = {a.x, a.z, b.x, b.z};
    float dy[4] = {a.y, a.w, b.y, b.w};

    int cx[4], cy[4], gp[4];
#pragma unroll
    for (int i = 0; i < 4; i++) {
        cx[i] = clampi((int)((float)(x + i) + dx[i]), W - 1);
        cy[i] = clampi((int)((float)y + dy[i]), H - 1);
        gp[i] = cy[i] * W + cx[i];
    }

    float2 g[4];
#pragma unroll
    for (int i = 0; i < 4; i++) g[i] = base[gp[i]];

    // disp out (planar [N,2,H,W]) — vectorized per plane
    float* db = disp_out + (size_t)n * 2 * HW;
    *(float4*)(db + p)      = make_float4(dx[0] + g[0].x, dx[1] + g[1].x,
                                          dx[2] + g[2].x, dx[3] + g[3].x);
    *(float4*)(db + HW + p) = make_float4(dy[0] + g[0].y, dy[1] + g[1].y,
                                          dy[2] + g[2].y, dy[3] + g[3].y);

    // num_touch scatter-add (counts are small integers; exact in f32)
    float* ntb = nt_out + (size_t)n * HW;
#pragma unroll
    for (int i = 0; i < 4; i++) atomicAdd(&ntb[gp[i]], 1.0f);

    // pred_cent [N,3,H,W] = (b, cx, cy)
    float* pb = pc_out + (size_t)n * 3 * HW;
    *(float4*)(pb + p) = make_float4((float)n, (float)n, (float)n, (float)n);
    *(float4*)(pb + HW + p) = make_float4((float)cx[0], (float)cx[1],
                                          (float)cx[2], (float)cx[3]);
    *(float4*)(pb + 2 * HW + p) = make_float4((float)cy[0], (float)cy[1],
                                              (float)cy[2], (float)cy[3]);
}

extern "C" void kernel_launch(void* const* d_in, const int* in_sizes, int n_in,
                              void* d_out, int out_size) {
    const float* pred_disp = (const float*)d_in[0];
    float* out = (float*)d_out;

    float* disp_out = out;                      // 2*NHW
    float* nt_out   = out + (size_t)2 * NHW;    // NHW
    float* pc_out   = out + (size_t)3 * NHW;    // 3*NHW

    float2* bufA;  cudaGetSymbolAddress((void**)&bufA, g_bufA);
    float2* bufB;  cudaGetSymbolAddress((void**)&bufB, g_bufB);

    dim3 grid(BLKS, NB);

    iter_first<<<grid, T>>>(pred_disp, bufA, nt_out);          // it 1 (+ nt zero)
    iter_mid  <<<grid, T>>>(bufA, bufB);                       // it 2
    iter_mid  <<<grid, T>>>(bufB, bufA);                       // it 3
    iter_last <<<grid, T>>>(bufA, disp_out, nt_out, pc_out);   // it 4
}